// round 9
// baseline (speedup 1.0000x reference)
#include <cuda_runtime.h>
#include <cstdint>

namespace {
constexpr int B_  = 2;
constexpr int H_  = 8;
constexpr int NQ_ = 2048;
constexpr int NK_ = 2048;
constexpr int D_  = 64;
constexpr int TQ_ = 16;
constexpr int TK_ = 16;
constexpr int ITERS = NK_ / TK_;     // 128
constexpr int NTHREADS = 256;        // 8 warps = 8 heads

// Q tile: 16 x 512, stride 516 (bank rotation 4): fragment loads conflict-free.
// K tile: 16 x 512, stride 516, RAW fp32 (relu+cvt at fragment load), cp.async.
// V tile: 16 x 512, stride 520 (rotation 8): phase-2 B-frag banks 8c+g+8n -> CF.
// S tile: 8 heads x 16 x 16, row stride 17 (SCALAR stores only -- odd stride).
constexpr int QK_STRIDE = 516;
constexpr int V_STRIDE  = 520;
constexpr int S_STRIDE  = 17;
constexpr int OFF_Q = 0;                         // 8256 floats
constexpr int OFF_K = 8256;                      // 8256
constexpr int OFF_V = 16512;                     // 8320
constexpr int OFF_S = 24832;                     // 2176
constexpr int S_HSTR = TQ_ * S_STRIDE;           // 272
constexpr int SMEM_FLOATS = OFF_S + H_ * S_HSTR; // 27008
constexpr size_t SMEM_BYTES = (size_t)SMEM_FLOATS * sizeof(float);  // 108032 -> 2 CTAs/SM
}

__device__ __forceinline__ int qk_addr(int row, int col) { return row * QK_STRIDE + col; }
__device__ __forceinline__ int v_addr (int row, int col) { return row * V_STRIDE  + col; }
__device__ __forceinline__ int s_addr (int h, int row, int k) { return h * S_HSTR + row * S_STRIDE + k; }

__device__ __forceinline__ uint32_t smem_u32(const void* p) {
    uint32_t a;
    asm("{ .reg .u64 t; cvta.to.shared.u64 t, %1; cvt.u32.u64 %0, t; }" : "=r"(a) : "l"(p));
    return a;
}
__device__ __forceinline__ uint32_t tf32r(float f) {
    uint32_t r; asm("cvt.rna.tf32.f32 %0, %1;" : "=r"(r) : "f"(f)); return r;
}
__device__ __forceinline__ float tf32f(float f) { return __uint_as_float(tf32r(f)); }
__device__ __forceinline__ float tf32relu(float f) { return __uint_as_float(tf32r(fmaxf(f, 0.f))); }

__device__ __forceinline__ void cp16(uint32_t dst, const float* src) {
    asm volatile("cp.async.cg.shared.global [%0], [%1], 16;" :: "r"(dst), "l"(src) : "memory");
}
__device__ __forceinline__ void cp_commit() { asm volatile("cp.async.commit_group;" ::: "memory"); }
__device__ __forceinline__ void cp_wait1()  { asm volatile("cp.async.wait_group 1;" ::: "memory"); }

// D += A(16x8,row) * B(8x8,col)   tf32 inputs, f32 accumulate
__device__ __forceinline__ void mma_tf32(float* d, const uint32_t* a, const uint32_t* b) {
    asm volatile(
        "mma.sync.aligned.m16n8k8.row.col.f32.tf32.tf32.f32 "
        "{%0,%1,%2,%3}, {%4,%5,%6,%7}, {%8,%9}, {%0,%1,%2,%3};"
        : "+f"(d[0]), "+f"(d[1]), "+f"(d[2]), "+f"(d[3])
        : "r"(a[0]), "r"(a[1]), "r"(a[2]), "r"(a[3]), "r"(b[0]), "r"(b[1]));
}

__global__ __launch_bounds__(NTHREADS, 2)
void linattn_mma(const float* __restrict__ Qg, const float* __restrict__ Kg,
                 const float* __restrict__ Vg, const float* __restrict__ Mg,
                 float* __restrict__ Og)
{
    extern __shared__ float sm[];
    float* Qs = sm + OFF_Q;
    float* Ks = sm + OFF_K;
    float* Vs = sm + OFF_V;
    float* Ss = sm + OFF_S;
    const uint32_t sb   = smem_u32(sm);
    const uint32_t sb_k = sb + OFF_K * 4u;
    const uint32_t sb_v = sb + OFF_V * 4u;

    const int tid  = threadIdx.x;
    const int warp = tid >> 5;          // warp == head h
    const int lane = tid & 31;
    const int g    = lane >> 2;         // 0..7
    const int c    = lane & 3;          // 0..3
    const int b    = blockIdx.y;
    const int q0   = blockIdx.x * TQ_;
    const int h    = warp;
    const int hcol = h * D_;

    // Normalize coords: one (q,k) pair per thread (16x16 = 256)
    const int nq = tid >> 4;
    const int nk = tid & 15;

    // ---- Load Q tile (relu + tf32 at store): 16 rows x 512 = 2048 float4 ----
    #pragma unroll
    for (int i = 0; i < 8; i++) {
        int idx = tid + NTHREADS * i;
        int q = idx >> 7, rem = idx & 127;
        int hh = rem >> 4, d4 = rem & 15;
        float4 v = *reinterpret_cast<const float4*>(
            Qg + (((size_t)(b * H_ + hh) * NQ_ + q0 + q) * D_ + d4 * 4));
        float4 t;
        t.x = tf32relu(v.x); t.y = tf32relu(v.y);
        t.z = tf32relu(v.z); t.w = tf32relu(v.w);
        *reinterpret_cast<float4*>(&Qs[qk_addr(q, hh * D_ + d4 * 4)]) = t;
    }

    // ---- Prologue: prefetch K(0) then V(0), separate groups ----
    #pragma unroll
    for (int i = 0; i < 8; i++) {
        int idx = tid + NTHREADS * i;
        int k = idx >> 7, rem = idx & 127;
        int hh = rem >> 4, d4 = rem & 15;
        cp16(sb_k + (uint32_t)(qk_addr(k, hh * D_ + d4 * 4)) * 4u,
             Kg + (((size_t)(b * H_ + hh) * NK_ + k) * D_ + d4 * 4));
    }
    cp_commit();
    #pragma unroll
    for (int i = 0; i < 8; i++) {
        int idx = tid + NTHREADS * i;
        int k = idx >> 7, rem = idx & 127;
        int hh = rem >> 4, d4 = rem & 15;
        cp16(sb_v + (uint32_t)(v_addr(k, hh * D_ + d4 * 4)) * 4u,
             Vg + (((size_t)(b * H_ + hh) * NK_ + k) * D_ + d4 * 4));
    }
    cp_commit();

    // Persistent O fragments: [ntile][4]  (16 q-rows x 64 d-cols)
    float oacc[8][4];
    #pragma unroll
    for (int n = 0; n < 8; n++)
        #pragma unroll
        for (int r = 0; r < 4; r++) oacc[n][r] = 0.f;

    for (int it = 0; it < ITERS; it++) {
        const int k0 = it * TK_;

        // ---- Mask prefetch (hidden under phase 1) ----
        float mv = Mg[(size_t)b * NQ_ * NK_ + (size_t)(q0 + nq) * NK_ + k0 + nk];

        cp_wait1();            // K(it) complete
        __syncthreads();

        // ---- Phase 1: S_h[16x16] = relu(Q) @ relu(K)^T ----
        float sacc[2][4];
        #pragma unroll
        for (int n = 0; n < 2; n++)
            #pragma unroll
            for (int r = 0; r < 4; r++) sacc[n][r] = 0.f;

        #pragma unroll
        for (int t = 0; t < 8; t++) {
            const int colb = hcol + 8 * t + c;
            uint32_t a[4], bb[2][2];
            a[0] = __float_as_uint(Qs[qk_addr(g,     colb)]);
            a[1] = __float_as_uint(Qs[qk_addr(g + 8, colb)]);
            a[2] = __float_as_uint(Qs[qk_addr(g,     colb + 4)]);
            a[3] = __float_as_uint(Qs[qk_addr(g + 8, colb + 4)]);
            #pragma unroll
            for (int n = 0; n < 2; n++) {
                bb[n][0] = tf32r(fmaxf(Ks[qk_addr(8 * n + g, colb)],     0.f));
                bb[n][1] = tf32r(fmaxf(Ks[qk_addr(8 * n + g, colb + 4)], 0.f));
            }
            #pragma unroll
            for (int n = 0; n < 2; n++)
                mma_tf32(sacc[n], a, bb[n]);
        }

        // ---- Store raw S (scalar stores: odd stride, float2 would misalign) ----
        #pragma unroll
        for (int n = 0; n < 2; n++) {
            Ss[s_addr(h, g,     8 * n + 2 * c)]     = sacc[n][0];
            Ss[s_addr(h, g,     8 * n + 2 * c + 1)] = sacc[n][1];
            Ss[s_addr(h, g + 8, 8 * n + 2 * c)]     = sacc[n][2];
            Ss[s_addr(h, g + 8, 8 * n + 2 * c + 1)] = sacc[n][3];
        }
        __syncthreads();       // all K reads done + S visible

        // ---- Prefetch K(it+1) ----
        if (it + 1 < ITERS) {
            const int kn = k0 + TK_;
            #pragma unroll
            for (int i = 0; i < 8; i++) {
                int idx = tid + NTHREADS * i;
                int k = idx >> 7, rem = idx & 127;
                int hh = rem >> 4, d4 = rem & 15;
                cp16(sb_k + (uint32_t)(qk_addr(k, hh * D_ + d4 * 4)) * 4u,
                     Kg + (((size_t)(b * H_ + hh) * NK_ + kn + k) * D_ + d4 * 4));
            }
        }
        cp_commit();

        // ---- Normalize in place: P = S * mask / sum_h(S) ----
        {
            float s[H_], den = 0.f;
            #pragma unroll
            for (int hh = 0; hh < H_; hh++) { s[hh] = Ss[s_addr(hh, nq, nk)]; den += s[hh]; }
            const float inv = __fdividef(mv, den);
            #pragma unroll
            for (int hh = 0; hh < H_; hh++)
                Ss[s_addr(hh, nq, nk)] = tf32f(s[hh] * inv);
        }

        cp_wait1();            // V(it) complete
        __syncthreads();       // P visible

        // ---- Phase 2: O_h += P_h[16x16] @ V_h[16x64] ----
        #pragma unroll
        for (int t = 0; t < 2; t++) {
            uint32_t a[4], bb[8][2];
            a[0] = __float_as_uint(Ss[s_addr(h, g,     8 * t + c)]);
            a[1] = __float_as_uint(Ss[s_addr(h, g + 8, 8 * t + c)]);
            a[2] = __float_as_uint(Ss[s_addr(h, g,     8 * t + c + 4)]);
            a[3] = __float_as_uint(Ss[s_addr(h, g + 8, 8 * t + c + 4)]);
            #pragma unroll
            for (int n = 0; n < 8; n++) {
                bb[n][0] = tf32r(Vs[v_addr(8 * t + c,     hcol + 8 * n + g)]);
                bb[n][1] = tf32r(Vs[v_addr(8 * t + c + 4, hcol + 8 * n + g)]);
            }
            #pragma unroll
            for (int n = 0; n < 8; n++)
                mma_tf32(oacc[n], a, bb[n]);
        }
        __syncthreads();       // all V reads done before overwrite

        // ---- Prefetch V(it+1) ----
        if (it + 1 < ITERS) {
            const int kn = k0 + TK_;
            #pragma unroll
            for (int i = 0; i < 8; i++) {
                int idx = tid + NTHREADS * i;
                int k = idx >> 7, rem = idx & 127;
                int hh = rem >> 4, d4 = rem & 15;
                cp16(sb_v + (uint32_t)(v_addr(k, hh * D_ + d4 * 4)) * 4u,
                     Vg + (((size_t)(b * H_ + hh) * NK_ + kn + k) * D_ + d4 * 4));
            }
        }
        cp_commit();
    }

    // ---- Epilogue: out = O + raw query ----
    #pragma unroll
    for (int n = 0; n < 8; n++) {
        const int q1 = q0 + g;
        const size_t base = ((size_t)(b * H_ + h) * NQ_ + q1) * D_ + 8 * n + 2 * c;
        const float2 r0 = *reinterpret_cast<const float2*>(Qg + base);
        *reinterpret_cast<float2*>(Og + base) =
            make_float2(oacc[n][0] + r0.x, oacc[n][1] + r0.y);
        const size_t base2 = base + 8 * (size_t)D_;   // row q1+8
        const float2 r1 = *reinterpret_cast<const float2*>(Qg + base2);
        *reinterpret_cast<float2*>(Og + base2) =
            make_float2(oacc[n][2] + r1.x, oacc[n][3] + r1.y);
    }
}

extern "C" void kernel_launch(void* const* d_in, const int* in_sizes, int n_in,
                              void* d_out, int out_size)
{
    (void)in_sizes; (void)n_in; (void)out_size;
    const float* Qg = (const float*)d_in[0];
    const float* Kg = (const float*)d_in[1];
    const float* Vg = (const float*)d_in[2];
    const float* Mg = (const float*)d_in[3];
    float* Og = (float*)d_out;

    static bool attr_set = false;
    if (!attr_set) {
        cudaFuncSetAttribute(linattn_mma,
                             cudaFuncAttributeMaxDynamicSharedMemorySize,
                             (int)SMEM_BYTES);
        attr_set = true;
    }

    dim3 grid(NQ_ / TQ_, B_);   // (128, 2) = 256 CTAs, 2 per SM, one wave
    linattn_mma<<<grid, NTHREADS, SMEM_BYTES>>>(Qg, Kg, Vg, Mg, Og);
}

// round 10
// speedup vs baseline: 1.0267x; 1.0267x over previous
#include <cuda_runtime.h>
#include <cstdint>

namespace {
constexpr int B_  = 2;
constexpr int H_  = 8;
constexpr int NQ_ = 2048;
constexpr int NK_ = 2048;
constexpr int D_  = 64;
constexpr int TQ_ = 32;
constexpr int TK_ = 32;
constexpr int ITERS = NK_ / TK_;     // 64
constexpr int NTHREADS = 512;        // 16 warps; phase1 warp=(head,mhalf), phase2 warp=(head,nhalf)

// K tile: 32 x 512, stride 516 (bank rotation 4), RAW fp32, cp.async target.
// V tile: 32 x 512, stride 520 (rotation 8): phase-2 B-frag banks 8c+g+8n -> CF.
// S tile: 8 heads x 32 x 32, row stride 33 (SCALAR stores only -- odd stride).
// Q lives in registers (loop-invariant phase-1 A fragments).
constexpr int QK_STRIDE = 516;
constexpr int V_STRIDE  = 520;
constexpr int S_STRIDE  = 33;
constexpr int OFF_K = 0;                          // 16512 floats
constexpr int OFF_V = 16512;                      // 16640
constexpr int OFF_S = 33152;                      // 8448
constexpr int S_HSTR = 32 * S_STRIDE;             // 1056
constexpr int SMEM_FLOATS = OFF_S + H_ * S_HSTR;  // 41600
constexpr size_t SMEM_BYTES = (size_t)SMEM_FLOATS * sizeof(float);  // 166400
}

__device__ __forceinline__ int qk_addr(int row, int col) { return row * QK_STRIDE + col; }
__device__ __forceinline__ int v_addr (int row, int col) { return row * V_STRIDE  + col; }
__device__ __forceinline__ int s_addr (int h, int row, int k) { return h * S_HSTR + row * S_STRIDE + k; }

__device__ __forceinline__ uint32_t smem_u32(const void* p) {
    uint32_t a;
    asm("{ .reg .u64 t; cvta.to.shared.u64 t, %1; cvt.u32.u64 %0, t; }" : "=r"(a) : "l"(p));
    return a;
}
__device__ __forceinline__ uint32_t tf32r(float f) {
    uint32_t r; asm("cvt.rna.tf32.f32 %0, %1;" : "=r"(r) : "f"(f)); return r;
}
__device__ __forceinline__ float tf32f(float f) { return __uint_as_float(tf32r(f)); }

__device__ __forceinline__ void cp16(uint32_t dst, const float* src) {
    asm volatile("cp.async.cg.shared.global [%0], [%1], 16;" :: "r"(dst), "l"(src) : "memory");
}
__device__ __forceinline__ void cp_commit() { asm volatile("cp.async.commit_group;" ::: "memory"); }
__device__ __forceinline__ void cp_wait1()  { asm volatile("cp.async.wait_group 1;" ::: "memory"); }

// D += A(16x8,row) * B(8x8,col)   tf32 inputs, f32 accumulate
__device__ __forceinline__ void mma_tf32(float* d, const uint32_t* a, const uint32_t* b) {
    asm volatile(
        "mma.sync.aligned.m16n8k8.row.col.f32.tf32.tf32.f32 "
        "{%0,%1,%2,%3}, {%4,%5,%6,%7}, {%8,%9}, {%0,%1,%2,%3};"
        : "+f"(d[0]), "+f"(d[1]), "+f"(d[2]), "+f"(d[3])
        : "r"(a[0]), "r"(a[1]), "r"(a[2]), "r"(a[3]), "r"(b[0]), "r"(b[1]));
}

__global__ __launch_bounds__(NTHREADS, 1)
void linattn_mma(const float* __restrict__ Qg, const float* __restrict__ Kg,
                 const float* __restrict__ Vg, const float* __restrict__ Mg,
                 float* __restrict__ Og)
{
    extern __shared__ float sm[];
    float* Ks = sm + OFF_K;
    float* Vs = sm + OFF_V;
    float* Ss = sm + OFF_S;
    const uint32_t sb   = smem_u32(sm);
    const uint32_t sb_k = sb + OFF_K * 4u;
    const uint32_t sb_v = sb + OFF_V * 4u;

    const int tid  = threadIdx.x;
    const int warp = tid >> 5;
    const int lane = tid & 31;
    const int g    = lane >> 2;         // 0..7
    const int c    = lane & 3;          // 0..3
    const int h    = warp & 7;          // head (both phases)
    const int wh   = warp >> 3;         // phase1: m-half; phase2: n-half
    const int b    = blockIdx.y;
    const int q0   = blockIdx.x * TQ_;
    const int hcol = h * D_;

    // ---- Load Q phase-1 A fragments into registers (loop-invariant) ----
    // Rows 16*wh+g, 16*wh+g+8 of head h; cols {8t+c, 8t+c+4} for t<8.
    uint32_t aq[8][4];
    {
        const size_t rbase = ((size_t)(b * H_ + h) * NQ_ + q0 + 16 * wh + g) * D_;
        #pragma unroll
        for (int t = 0; t < 8; t++) {
            const int col = 8 * t + c;
            aq[t][0] = tf32r(fmaxf(Qg[rbase + col],                  0.f));
            aq[t][1] = tf32r(fmaxf(Qg[rbase + 8 * (size_t)D_ + col], 0.f));
            aq[t][2] = tf32r(fmaxf(Qg[rbase + col + 4],                  0.f));
            aq[t][3] = tf32r(fmaxf(Qg[rbase + 8 * (size_t)D_ + col + 4], 0.f));
        }
    }

    // ---- Prologue: prefetch K(0) then V(0), separate groups ----
    #pragma unroll
    for (int i = 0; i < 8; i++) {
        int idx = tid + NTHREADS * i;               // 4096 float4
        int k = idx >> 7, rem = idx & 127;
        int hh = rem >> 4, d4 = rem & 15;
        cp16(sb_k + (uint32_t)(qk_addr(k, hh * D_ + d4 * 4)) * 4u,
             Kg + (((size_t)(b * H_ + hh) * NK_ + k) * D_ + d4 * 4));
    }
    cp_commit();
    #pragma unroll
    for (int i = 0; i < 8; i++) {
        int idx = tid + NTHREADS * i;
        int k = idx >> 7, rem = idx & 127;
        int hh = rem >> 4, d4 = rem & 15;
        cp16(sb_v + (uint32_t)(v_addr(k, hh * D_ + d4 * 4)) * 4u,
             Vg + (((size_t)(b * H_ + hh) * NK_ + k) * D_ + d4 * 4));
    }
    cp_commit();

    // Phase-2 persistent O fragments: warp (h, nh) owns O[32 rows x 32 cols].
    float oacc[2][4][4];
    #pragma unroll
    for (int m = 0; m < 2; m++)
        #pragma unroll
        for (int n = 0; n < 4; n++)
            #pragma unroll
            for (int r = 0; r < 4; r++) oacc[m][n][r] = 0.f;

    // Normalize coords: 2 (q,k) pairs per thread
    const int nq = tid >> 5;            // 0..15 (j adds 16)
    const int nk = tid & 31;

    for (int it = 0; it < ITERS; it++) {
        const int k0 = it * TK_;

        // ---- Mask prefetch (hidden under phase 1) ----
        float mv0 = Mg[(size_t)b * NQ_ * NK_ + (size_t)(q0 + nq) * NK_ + k0 + nk];
        float mv1 = Mg[(size_t)b * NQ_ * NK_ + (size_t)(q0 + nq + 16) * NK_ + k0 + nk];

        cp_wait1();            // K(it) complete
        __syncthreads();

        // ---- Phase 1: warp (h, mh=wh): S_h[16x32] = relu(Q)@relu(K)^T ----
        float sacc[4][4];
        #pragma unroll
        for (int n = 0; n < 4; n++)
            #pragma unroll
            for (int r = 0; r < 4; r++) sacc[n][r] = 0.f;

        #pragma unroll
        for (int t = 0; t < 8; t++) {
            const int colb = hcol + 8 * t + c;
            uint32_t bb[4][2];
            #pragma unroll
            for (int n = 0; n < 4; n++) {
                bb[n][0] = tf32r(fmaxf(Ks[qk_addr(8 * n + g, colb)],     0.f));
                bb[n][1] = tf32r(fmaxf(Ks[qk_addr(8 * n + g, colb + 4)], 0.f));
            }
            #pragma unroll
            for (int n = 0; n < 4; n++)
                mma_tf32(sacc[n], aq[t], bb[n]);
        }

        // ---- Store raw S (scalar stores -- odd stride 33) ----
        {
            const int r0 = 16 * wh + g;
            #pragma unroll
            for (int n = 0; n < 4; n++) {
                Ss[s_addr(h, r0,     8 * n + 2 * c)]     = sacc[n][0];
                Ss[s_addr(h, r0,     8 * n + 2 * c + 1)] = sacc[n][1];
                Ss[s_addr(h, r0 + 8, 8 * n + 2 * c)]     = sacc[n][2];
                Ss[s_addr(h, r0 + 8, 8 * n + 2 * c + 1)] = sacc[n][3];
            }
        }
        __syncthreads();       // all K reads done + S visible

        // ---- Prefetch K(it+1) ----
        if (it + 1 < ITERS) {
            const int kn = k0 + TK_;
            #pragma unroll
            for (int i = 0; i < 8; i++) {
                int idx = tid + NTHREADS * i;
                int k = idx >> 7, rem = idx & 127;
                int hh = rem >> 4, d4 = rem & 15;
                cp16(sb_k + (uint32_t)(qk_addr(k, hh * D_ + d4 * 4)) * 4u,
                     Kg + (((size_t)(b * H_ + hh) * NK_ + kn + k) * D_ + d4 * 4));
            }
        }
        cp_commit();           // committed even when empty (uniform group count)

        // ---- Normalize in place: P = S * mask / sum_h(S) ----
        #pragma unroll
        for (int j = 0; j < 2; j++) {
            const int q = nq + 16 * j;
            const float mval = j ? mv1 : mv0;
            float s[H_], den = 0.f;
            #pragma unroll
            for (int hh = 0; hh < H_; hh++) { s[hh] = Ss[s_addr(hh, q, nk)]; den += s[hh]; }
            const float inv = __fdividef(mval, den);
            #pragma unroll
            for (int hh = 0; hh < H_; hh++)
                Ss[s_addr(hh, q, nk)] = tf32f(s[hh] * inv);
        }

        cp_wait1();            // V(it) complete
        __syncthreads();       // P visible

        // ---- Phase 2: warp (h, nh=wh): O[32 x 32cols] += P_h @ V_h ----
        const int ncol = hcol + 32 * wh;
        #pragma unroll
        for (int t = 0; t < 4; t++) {
            uint32_t a[2][4], bb[4][2];
            #pragma unroll
            for (int m = 0; m < 2; m++) {
                a[m][0] = __float_as_uint(Ss[s_addr(h, 16 * m + g,     8 * t + c)]);
                a[m][1] = __float_as_uint(Ss[s_addr(h, 16 * m + g + 8, 8 * t + c)]);
                a[m][2] = __float_as_uint(Ss[s_addr(h, 16 * m + g,     8 * t + c + 4)]);
                a[m][3] = __float_as_uint(Ss[s_addr(h, 16 * m + g + 8, 8 * t + c + 4)]);
            }
            #pragma unroll
            for (int n = 0; n < 4; n++) {
                bb[n][0] = tf32r(Vs[v_addr(8 * t + c,     ncol + 8 * n + g)]);
                bb[n][1] = tf32r(Vs[v_addr(8 * t + c + 4, ncol + 8 * n + g)]);
            }
            #pragma unroll
            for (int m = 0; m < 2; m++)
                #pragma unroll
                for (int n = 0; n < 4; n++)
                    mma_tf32(oacc[m][n], a[m], bb[n]);
        }
        __syncthreads();       // all V reads done before overwrite

        // ---- Prefetch V(it+1) ----
        if (it + 1 < ITERS) {
            const int kn = k0 + TK_;
            #pragma unroll
            for (int i = 0; i < 8; i++) {
                int idx = tid + NTHREADS * i;
                int k = idx >> 7, rem = idx & 127;
                int hh = rem >> 4, d4 = rem & 15;
                cp16(sb_v + (uint32_t)(v_addr(k, hh * D_ + d4 * 4)) * 4u,
                     Vg + (((size_t)(b * H_ + hh) * NK_ + kn + k) * D_ + d4 * 4));
            }
        }
        cp_commit();
    }

    // ---- Epilogue: out = O + raw query (warp covers rows 0..31, cols 32*wh..+32) ----
    #pragma unroll
    for (int m = 0; m < 2; m++)
        #pragma unroll
        for (int n = 0; n < 4; n++) {
            const int q1 = q0 + 16 * m + g;
            const size_t base = ((size_t)(b * H_ + h) * NQ_ + q1) * D_ + 32 * wh + 8 * n + 2 * c;
            const float2 r0 = *reinterpret_cast<const float2*>(Qg + base);
            *reinterpret_cast<float2*>(Og + base) =
                make_float2(oacc[m][n][0] + r0.x, oacc[m][n][1] + r0.y);
            const size_t base2 = base + 8 * (size_t)D_;   // row q1+8
            const float2 r1 = *reinterpret_cast<const float2*>(Qg + base2);
            *reinterpret_cast<float2*>(Og + base2) =
                make_float2(oacc[m][n][2] + r1.x, oacc[m][n][3] + r1.y);
        }
}

extern "C" void kernel_launch(void* const* d_in, const int* in_sizes, int n_in,
                              void* d_out, int out_size)
{
    (void)in_sizes; (void)n_in; (void)out_size;
    const float* Qg = (const float*)d_in[0];
    const float* Kg = (const float*)d_in[1];
    const float* Vg = (const float*)d_in[2];
    const float* Mg = (const float*)d_in[3];
    float* Og = (float*)d_out;

    static bool attr_set = false;
    if (!attr_set) {
        cudaFuncSetAttribute(linattn_mma,
                             cudaFuncAttributeMaxDynamicSharedMemorySize,
                             (int)SMEM_BYTES);
        attr_set = true;
    }

    dim3 grid(NQ_ / TQ_, B_);   // (64, 2) = 128 CTAs, one wave
    linattn_mma<<<grid, NTHREADS, SMEM_BYTES>>>(Qg, Kg, Vg, Mg, Og);
}